// round 6
// baseline (speedup 1.0000x reference)
#include <cuda_runtime.h>

// Problem constants
#define TS   1000
#define BTOT 2048
#define HE   64     // encoder hidden
#define HD   65     // decoder hidden
#define GE   256    // 4*HE
#define GD   260    // 4*HD
#define NB   7      // batch elements per block
#define NGRID 296   // 2 CTAs per SM on 148 SMs
#define NTH  128    // threads per block
#define HSTR 68     // h row stride (16B-aligned rows)

typedef unsigned long long u64;

__device__ __forceinline__ u64 pack2(float lo, float hi){
    u64 r; asm("mov.b64 %0, {%1, %2};" : "=l"(r) : "f"(lo), "f"(hi)); return r;
}
__device__ __forceinline__ float2 unpk(u64 v){
    float2 f; asm("mov.b64 {%0, %1}, %2;" : "=f"(f.x), "=f"(f.y) : "l"(v)); return f;
}
__device__ __forceinline__ u64 ffma2(u64 a, u64 b, u64 c){
    u64 d; asm("fma.rn.f32x2 %0, %1, %2, %3;" : "=l"(d) : "l"(a), "l"(b), "l"(c)); return d;
}
// accurate sigmoid (recurrent path: i, f gates)
__device__ __forceinline__ float sigf(float x){
    return __fdividef(1.0f, 1.0f + __expf(-x));
}
// accurate tanh (recurrent path: g gate)
__device__ __forceinline__ float tanhf_(float x){
    return fmaf(2.0f, sigf(2.0f * x), -1.0f);
}
// fast tanh via MUFU.TANH (non-recurrent path only)
__device__ __forceinline__ float tanha(float x){
    float y; asm("tanh.approx.f32 %0, %1;" : "=f"(y) : "f"(x)); return y;
}
// fast sigmoid via MUFU.TANH (o gate only)
__device__ __forceinline__ float siga(float x){
    return fmaf(0.5f, tanha(0.5f * x), 0.5f);
}

__global__ void __launch_bounds__(NTH, 2)
lstm_seq2seq_kernel(const float* __restrict__ input,   // (T,B,1)
                    const float* __restrict__ speed,   // (B,1)
                    const float* __restrict__ target,  // (T,B,1)
                    const float* __restrict__ eWih,    // (256,1)
                    const float* __restrict__ eWhh,    // (256,64)
                    const float* __restrict__ ebih,    // (256)
                    const float* __restrict__ ebhh,    // (256)
                    const float* __restrict__ dWih,    // (260,1)
                    const float* __restrict__ dWhh,    // (260,65)
                    const float* __restrict__ dbih,    // (260)
                    const float* __restrict__ dbhh,    // (260)
                    const float* __restrict__ linW,    // (1,65)
                    const float* __restrict__ linb,    // (1)
                    const float* __restrict__ denW,    // (1,1)
                    const float* __restrict__ denb,    // (1)
                    float* __restrict__ out)           // (T,B,1)
{
    __shared__ __align__(16) float h_s[NB][HSTR];   // hidden state per batch
    __shared__ __align__(16) float g_s[NB][GD];     // gates (reused as c scratch at transition)
    __shared__ float x_s[2][NB];                    // double-buffered scalar inputs
    __shared__ __align__(16) float wx_s[4][HSTR];   // decoder leftover rows 256..259
    __shared__ float wih_x[4], b_x[4];
    __shared__ float lw_s[HD];
    __shared__ float sp_s[NB];

    const int tid  = threadIdx.x;
    const int lane = tid & 31;
    const int wrp  = tid >> 5;         // warp 0..3
    const int b0   = blockIdx.x * NB;
    const int r    = tid;              // thread owns gate rows r and r+128

    // ---------------- encoder weights: rows r and r+128 into registers ----------------
    u64 wpA[32], wpB[32];
    {
        const ulonglong2* wrA = (const ulonglong2*)(eWhh + r * HE);
        const ulonglong2* wrB = (const ulonglong2*)(eWhh + (r + 128) * HE);
        #pragma unroll
        for (int j = 0; j < 16; j++){
            ulonglong2 va = wrA[j]; wpA[2*j] = va.x; wpA[2*j+1] = va.y;
            ulonglong2 vb = wrB[j]; wpB[2*j] = vb.x; wpB[2*j+1] = vb.y;
        }
    }
    float wihA  = eWih[r],           wihB  = eWih[r + 128];
    float biasA = ebih[r] + ebhh[r], biasB = ebih[r + 128] + ebhh[r + 128];

    // zero hidden state
    for (int i = tid; i < NB * HSTR; i += NTH) ((float*)h_s)[i] = 0.0f;

    // encoder activation: flat n = tid + 128*j over NB*HE = 448 items (4 per thread)
    float c_e[4] = {0.f, 0.f, 0.f, 0.f};

    const bool bvalid = (tid < NB) && (b0 + tid < BTOT);
    if (tid < NB) x_s[0][tid] = bvalid ? input[b0 + tid] : 0.0f;
    __syncthreads();

    // ================= encoder recurrence =================
    for (int t = 0; t < TS; t++){
        const float* xr = x_s[t & 1];
        float xnext = 0.0f;
        if (bvalid && t + 1 < TS) xnext = input[(t + 1) * BTOT + b0 + tid];

        // GEMM phase: rows r, r+128 over all NB batches (broadcast h reads)
        #pragma unroll
        for (int bb = 0; bb < NB; bb++){
            const ulonglong2* hp = (const ulonglong2*)h_s[bb];
            u64 a0 = 0ull, a1 = 0ull, d0 = 0ull, d1 = 0ull;
            #pragma unroll
            for (int k = 0; k < 16; k++){
                ulonglong2 hv = hp[k];
                a0 = ffma2(hv.x, wpA[2*k],     a0);
                a1 = ffma2(hv.y, wpA[2*k + 1], a1);
                d0 = ffma2(hv.x, wpB[2*k],     d0);
                d1 = ffma2(hv.y, wpB[2*k + 1], d1);
            }
            float2 p = unpk(a0), q = unpk(a1);
            float2 s = unpk(d0), w = unpk(d1);
            g_s[bb][r]       = (p.x + p.y) + (q.x + q.y) + fmaf(wihA, xr[bb], biasA);
            g_s[bb][r + 128] = (s.x + s.y) + (w.x + w.y) + fmaf(wihB, xr[bb], biasB);
        }
        __syncthreads();

        // activation phase (PyTorch gate order i,f,g,o)
        #pragma unroll
        for (int j = 0; j < 4; j++){
            int n = tid + NTH * j;
            if (j < 3 || n < NB * HE){
                int bb = n >> 6, uu = n & 63;
                float ig = g_s[bb][uu];
                float fg = g_s[bb][HE + uu];
                float gg = g_s[bb][2*HE + uu];
                float og = g_s[bb][3*HE + uu];
                float cc = sigf(fg) * c_e[j] + sigf(ig) * tanhf_(gg);
                c_e[j] = cc;
                h_s[bb][uu] = siga(og) * tanha(cc);
            }
        }
        if (tid < NB) x_s[(t + 1) & 1][tid] = xnext;
        __syncthreads();
    }

    // ================= encoder -> decoder transition =================
    // park encoder c in g_s (same item layout)
    #pragma unroll
    for (int j = 0; j < 4; j++){
        int n = tid + NTH * j;
        if (j < 3 || n < NB * HE){
            int bb = n >> 6, uu = n & 63;
            g_s[bb][uu] = c_e[j];
        }
    }

    if (tid < NB){
        float sp = bvalid ? fmaf(speed[b0 + tid], denW[0], denb[0]) : 0.0f;
        sp_s[tid]     = sp;
        h_s[tid][HE]  = sp;     // 65th hidden element
        x_s[0][tid]   = 0.0f;   // teacher forcing: x_dec[0] = 0
    }
    if (tid < HD) lw_s[tid] = linW[tid];

    // decoder weights: rows r and r+128 (65 wide) into registers
    float wlastA, wlastB;
    {
        const float* wrA = dWhh + r * HD;
        const float* wrB = dWhh + (r + 128) * HD;
        #pragma unroll
        for (int j = 0; j < 32; j++){
            wpA[j] = pack2(wrA[2*j], wrA[2*j+1]);
            wpB[j] = pack2(wrB[2*j], wrB[2*j+1]);
        }
        wlastA = wrA[64]; wlastB = wrB[64];
    }
    wihA  = dWih[r];                 wihB  = dWih[r + 128];
    biasA = dbih[r] + dbhh[r];       biasB = dbih[r + 128] + dbhh[r + 128];

    // leftover rows 256..259 -> shared
    if (tid < 4){
        const float* wr = dWhh + (GE + tid) * HD;
        for (int k = 0; k < HD; k++) wx_s[tid][k] = wr[k];
        wih_x[tid] = dWih[GE + tid];
        b_x[tid]   = dbih[GE + tid] + dbhh[GE + tid];
    }
    __syncthreads();

    // decoder activation items: flat n = tid + 128*j over NB*HD = 455 items
    int   db[4], du[4];
    float dc[4];
    #pragma unroll
    for (int j = 0; j < 4; j++){
        int n = tid + NTH * j;
        bool v = (n < NB * HD);
        int bb = v ? (n / HD) : 0;
        int uu = v ? (n - bb * HD) : 0;
        db[j] = bb; du[j] = uu;
        dc[j] = v ? ((uu < HE) ? g_s[bb][uu] : sp_s[bb]) : 0.0f;
    }
    float lb_ = linb[0];
    __syncthreads();   // all c-init reads of g_s done before GEMM overwrites it

    // ================= decoder recurrence =================
    for (int t = 0; t < TS; t++){
        const float* xr = x_s[t & 1];

        // output projection for previous step's h (h_s stable during GEMM phase)
        if (bvalid && t > 0){
            float a0 = lb_, a1 = 0.f, a2 = 0.f, a3 = 0.f;
            #pragma unroll
            for (int k = 0; k < 64; k += 4){
                a0 = fmaf(lw_s[k  ], h_s[tid][k  ], a0);
                a1 = fmaf(lw_s[k+1], h_s[tid][k+1], a1);
                a2 = fmaf(lw_s[k+2], h_s[tid][k+2], a2);
                a3 = fmaf(lw_s[k+3], h_s[tid][k+3], a3);
            }
            a0 = fmaf(lw_s[64], h_s[tid][64], a0);
            out[(t - 1) * BTOT + b0 + tid] = (a0 + a1) + (a2 + a3);
        }

        float xnext = 0.0f;
        if (bvalid && t < TS - 1) xnext = target[t * BTOT + b0 + tid]; // x_dec[t+1] = target[t]

        // GEMM phase: rows r, r+128 over all NB batches
        #pragma unroll
        for (int bb = 0; bb < NB; bb++){
            const ulonglong2* hp = (const ulonglong2*)h_s[bb];
            u64 a0 = 0ull, a1 = 0ull, d0 = 0ull, d1 = 0ull;
            #pragma unroll
            for (int k = 0; k < 16; k++){
                ulonglong2 hv = hp[k];
                a0 = ffma2(hv.x, wpA[2*k],     a0);
                a1 = ffma2(hv.y, wpA[2*k + 1], a1);
                d0 = ffma2(hv.x, wpB[2*k],     d0);
                d1 = ffma2(hv.y, wpB[2*k + 1], d1);
            }
            float hlast = h_s[bb][HE];
            float2 p = unpk(a0), q = unpk(a1);
            float2 s = unpk(d0), w = unpk(d1);
            g_s[bb][r]       = (p.x + p.y) + (q.x + q.y)
                             + fmaf(wlastA, hlast, fmaf(wihA, xr[bb], biasA));
            g_s[bb][r + 128] = (s.x + s.y) + (w.x + w.y)
                             + fmaf(wlastB, hlast, fmaf(wihB, xr[bb], biasB));
        }
        // leftover rows 256..259: warp w -> row 256+w, lanes 0..6 -> batches
        if (lane < NB){
            const int rr = wrp, bb = lane;
            float acc = fmaf(wih_x[rr], xr[bb], b_x[rr]);
            #pragma unroll
            for (int k = 0; k < HD; k++) acc = fmaf(wx_s[rr][k], h_s[bb][k], acc);
            g_s[bb][GE + rr] = acc;
        }
        __syncthreads();

        // activation phase, H = 65
        #pragma unroll
        for (int j = 0; j < 4; j++){
            if (j < 3 || tid + NTH * j < NB * HD){
                int bb = db[j], uu = du[j];
                float ig = g_s[bb][uu];
                float fg = g_s[bb][HD + uu];
                float gg = g_s[bb][2*HD + uu];
                float og = g_s[bb][3*HD + uu];
                float cc = sigf(fg) * dc[j] + sigf(ig) * tanhf_(gg);
                dc[j] = cc;
                h_s[bb][uu] = siga(og) * tanha(cc);
            }
        }
        if (tid < NB) x_s[(t + 1) & 1][tid] = xnext;
        __syncthreads();
    }

    // final output (t = TS-1)
    if (bvalid){
        float a0 = lb_, a1 = 0.f, a2 = 0.f, a3 = 0.f;
        #pragma unroll
        for (int k = 0; k < 64; k += 4){
            a0 = fmaf(lw_s[k  ], h_s[tid][k  ], a0);
            a1 = fmaf(lw_s[k+1], h_s[tid][k+1], a1);
            a2 = fmaf(lw_s[k+2], h_s[tid][k+2], a2);
            a3 = fmaf(lw_s[k+3], h_s[tid][k+3], a3);
        }
        a0 = fmaf(lw_s[64], h_s[tid][64], a0);
        out[(TS - 1) * BTOT + b0 + tid] = (a0 + a1) + (a2 + a3);
    }
}

extern "C" void kernel_launch(void* const* d_in, const int* in_sizes, int n_in,
                              void* d_out, int out_size)
{
    const float* input  = (const float*)d_in[0];
    const float* speed  = (const float*)d_in[1];
    const float* target = (const float*)d_in[2];
    const float* eWih   = (const float*)d_in[3];
    const float* eWhh   = (const float*)d_in[4];
    const float* ebih   = (const float*)d_in[5];
    const float* ebhh   = (const float*)d_in[6];
    const float* dWih   = (const float*)d_in[7];
    const float* dWhh   = (const float*)d_in[8];
    const float* dbih   = (const float*)d_in[9];
    const float* dbhh   = (const float*)d_in[10];
    const float* linW   = (const float*)d_in[11];
    const float* linb   = (const float*)d_in[12];
    const float* denW   = (const float*)d_in[13];
    const float* denb   = (const float*)d_in[14];
    float* outp = (float*)d_out;

    dim3 grid(NGRID);   // 296 blocks = 2 CTAs per SM, balanced
    dim3 block(NTH);    // 128 threads
    lstm_seq2seq_kernel<<<grid, block>>>(input, speed, target,
                                         eWih, eWhh, ebih, ebhh,
                                         dWih, dWhh, dbih, dbhh,
                                         linW, linb, denW, denb, outp);
}